// round 4
// baseline (speedup 1.0000x reference)
#include <cuda_runtime.h>

// Attention: B=2, H=16, S=2048, D=64 (fp32), mask int32 [B,1,S,S]
// Outputs concatenated in d_out: out [B,H,S,D] then p_attn [B,H,S,S].
//
// Strategy: per (b,h,qtile=64) block.
//   Pass 1: QK^T tiles -> raw masked scores written to p_attn (scratch),
//           online rowmax m and sumexp l kept in registers (flash-style).
//   Pass 2: re-read scores (same thread -> no fence), p = exp(s-m)/l,
//           overwrite p_attn with final p, accumulate out += p @ V.

#define S_LEN 2048
#define D_HEAD 64

__global__ __launch_bounds__(256)
void attn_fused_kernel(const float* __restrict__ Q,
                       const float* __restrict__ K,
                       const float* __restrict__ V,
                       const int*   __restrict__ M,
                       float* __restrict__ Out,
                       float* __restrict__ P)
{
    __shared__ float sA[64 * 68]; // pass1: Q^T [d][q] ; pass2: V [k][d]
    __shared__ float sB[64 * 72]; // pass1: K^T [d][k] ; pass2: P^T [k][q]

    const int tid = threadIdx.x;
    const int tx  = tid & 15;   // k (pass1) / d (pass2) micro-col group
    const int ty  = tid >> 4;   // q micro-row group
    const int bh  = blockIdx.y;           // 0..31  (b*16 + h)
    const int q0  = blockIdx.x * 64;

    const float* qp = Q + ((size_t)bh * S_LEN + q0) * D_HEAD;
    const float* kp = K + (size_t)bh * S_LEN * D_HEAD;
    const float* vp = V + (size_t)bh * S_LEN * D_HEAD;
    const int*   mp = M + (size_t)(bh >> 4) * S_LEN * S_LEN + (size_t)q0 * S_LEN;
    float* pp = P   + ((size_t)bh * S_LEN + q0) * S_LEN;
    float* op = Out + ((size_t)bh * S_LEN + q0) * D_HEAD;

    // ---- load Q tile (64x64) transposed into sA[d][q] ----
    {
        const int r = tid >> 4;
        const int c = (tid & 15) * 4;
        #pragma unroll
        for (int it = 0; it < 4; ++it) {
            const int row = r + it * 16;
            float4 val = *(const float4*)(qp + row * D_HEAD + c);
            sA[(c + 0) * 68 + row] = val.x;
            sA[(c + 1) * 68 + row] = val.y;
            sA[(c + 2) * 68 + row] = val.z;
            sA[(c + 3) * 68 + row] = val.w;
        }
    }

    float m_run[4], l_run[4];
    #pragma unroll
    for (int i = 0; i < 4; ++i) { m_run[i] = -3.0e38f; l_run[i] = 0.0f; }

    // ================= Pass 1: scores + online stats =================
    for (int kt = 0; kt < S_LEN; kt += 64) {
        __syncthreads();
        // load K tile transposed into sB[d][k]
        {
            const int r = tid >> 4;
            const int c = (tid & 15) * 4;
            #pragma unroll
            for (int it = 0; it < 4; ++it) {
                const int row = r + it * 16;
                float4 val = *(const float4*)(kp + (size_t)(kt + row) * D_HEAD + c);
                sB[(c + 0) * 68 + row] = val.x;
                sB[(c + 1) * 68 + row] = val.y;
                sB[(c + 2) * 68 + row] = val.z;
                sB[(c + 3) * 68 + row] = val.w;
            }
        }
        __syncthreads();

        float acc[4][4];
        #pragma unroll
        for (int i = 0; i < 4; ++i)
            #pragma unroll
            for (int j = 0; j < 4; ++j) acc[i][j] = 0.0f;

        #pragma unroll 16
        for (int d = 0; d < 64; ++d) {
            float4 a = *(const float4*)(sA + d * 68 + 4 * ty);
            float4 b = *(const float4*)(sB + d * 68 + 4 * tx);
            const float av[4] = {a.x, a.y, a.z, a.w};
            const float bv[4] = {b.x, b.y, b.z, b.w};
            #pragma unroll
            for (int i = 0; i < 4; ++i)
                #pragma unroll
                for (int j = 0; j < 4; ++j)
                    acc[i][j] += av[i] * bv[j];
        }

        #pragma unroll
        for (int i = 0; i < 4; ++i) {
            const int qr = 4 * ty + i;
            const int4 mv = *(const int4*)(mp + (size_t)qr * S_LEN + kt + 4 * tx);
            const float s0 = mv.x ? acc[i][0] * 0.125f : -1.0e9f;
            const float s1 = mv.y ? acc[i][1] * 0.125f : -1.0e9f;
            const float s2 = mv.z ? acc[i][2] * 0.125f : -1.0e9f;
            const float s3 = mv.w ? acc[i][3] * 0.125f : -1.0e9f;
            *(float4*)(pp + (size_t)qr * S_LEN + kt + 4 * tx) =
                make_float4(s0, s1, s2, s3);

            float tmax = fmaxf(fmaxf(s0, s1), fmaxf(s2, s3));
            #pragma unroll
            for (int off = 8; off > 0; off >>= 1)
                tmax = fmaxf(tmax, __shfl_xor_sync(0xffffffffu, tmax, off, 16));
            const float m_new = fmaxf(m_run[i], tmax);
            float es = __expf(s0 - m_new) + __expf(s1 - m_new)
                     + __expf(s2 - m_new) + __expf(s3 - m_new);
            #pragma unroll
            for (int off = 8; off > 0; off >>= 1)
                es += __shfl_xor_sync(0xffffffffu, es, off, 16);
            l_run[i] = l_run[i] * __expf(m_run[i] - m_new) + es;
            m_run[i] = m_new;
        }
    }

    float inv_l[4];
    #pragma unroll
    for (int i = 0; i < 4; ++i) inv_l[i] = 1.0f / l_run[i];

    float acc2[4][4];
    #pragma unroll
    for (int i = 0; i < 4; ++i)
        #pragma unroll
        for (int j = 0; j < 4; ++j) acc2[i][j] = 0.0f;

    // ================= Pass 2: finalize p, out += p @ V =================
    for (int kt = 0; kt < S_LEN; kt += 64) {
        __syncthreads();
        // load V tile directly: sA[k][d]
        {
            const int r = tid >> 4;
            const int c = (tid & 15) * 4;
            #pragma unroll
            for (int it = 0; it < 4; ++it) {
                const int row = r + it * 16;
                float4 val = *(const float4*)(vp + (size_t)(kt + row) * D_HEAD + c);
                *(float4*)(sA + row * 68 + c) = val;
            }
        }
        // re-read own raw scores, finalize p, write p, stash p^T in sB[k][q]
        #pragma unroll
        for (int i = 0; i < 4; ++i) {
            const int qr = 4 * ty + i;
            const float4 sv = *(const float4*)(pp + (size_t)qr * S_LEN + kt + 4 * tx);
            const float p0 = __expf(sv.x - m_run[i]) * inv_l[i];
            const float p1 = __expf(sv.y - m_run[i]) * inv_l[i];
            const float p2 = __expf(sv.z - m_run[i]) * inv_l[i];
            const float p3 = __expf(sv.w - m_run[i]) * inv_l[i];
            *(float4*)(pp + (size_t)qr * S_LEN + kt + 4 * tx) =
                make_float4(p0, p1, p2, p3);
            sB[(4 * tx + 0) * 72 + qr] = p0;
            sB[(4 * tx + 1) * 72 + qr] = p1;
            sB[(4 * tx + 2) * 72 + qr] = p2;
            sB[(4 * tx + 3) * 72 + qr] = p3;
        }
        __syncthreads();

        #pragma unroll 16
        for (int kk = 0; kk < 64; ++kk) {
            float4 a = *(const float4*)(sB + kk * 72 + 4 * ty);
            float4 b = *(const float4*)(sA + kk * 68 + 4 * tx);
            const float av[4] = {a.x, a.y, a.z, a.w};
            const float bv[4] = {b.x, b.y, b.z, b.w};
            #pragma unroll
            for (int i = 0; i < 4; ++i)
                #pragma unroll
                for (int j = 0; j < 4; ++j)
                    acc2[i][j] += av[i] * bv[j];
        }
    }

    #pragma unroll
    for (int i = 0; i < 4; ++i) {
        *(float4*)(op + (size_t)(4 * ty + i) * D_HEAD + 4 * tx) =
            make_float4(acc2[i][0], acc2[i][1], acc2[i][2], acc2[i][3]);
    }
}

extern "C" void kernel_launch(void* const* d_in, const int* in_sizes, int n_in,
                              void* d_out, int out_size)
{
    const float* q = (const float*)d_in[0];
    const float* k = (const float*)d_in[1];
    const float* v = (const float*)d_in[2];
    const int*   m = (const int*)d_in[3];
    float* out = (float*)d_out;
    float* p   = out + (size_t)2 * 16 * 2048 * 64;  // p_attn region after out

    dim3 grid(S_LEN / 64, 2 * 16);
    attn_fused_kernel<<<grid, 256>>>(q, k, v, m, out, p);
}